// round 11
// baseline (speedup 1.0000x reference)
#include <cuda_runtime.h>
#include <cstddef>

#define BN 4
#define NN 1024
#define CC 64
#define ROWS (BN*NN)   // 4096
#define IB 8           // i-rows per logits block (one warp per i-row)
#define JC 128         // j per tile

typedef unsigned long long ull;

// device scratch (no allocation allowed)
__device__ float g_A [ROWS*CC];          // e^{2*z1}, clamped, [b*N+i][c]
__device__ float g_uT[BN*CC*NN];         // e^{2*z2}, clamped, transposed [b][c][j]

__device__ __forceinline__ float rcp_fast(float x){
    float y; asm("rcp.approx.f32 %0, %1;" : "=f"(y) : "f"(x)); return y;
}
__device__ __forceinline__ float ex2_fast(float x){
    float y; asm("ex2.approx.f32 %0, %1;" : "=f"(y) : "f"(x)); return y;
}
__device__ __forceinline__ ull fma2(ull a, ull b, ull c){
    ull d; asm("fma.rn.f32x2 %0, %1, %2, %3;" : "=l"(d) : "l"(a), "l"(b), "l"(c)); return d;
}
__device__ __forceinline__ ull mul2(ull a, ull b){
    ull d; asm("mul.rn.f32x2 %0, %1, %2;" : "=l"(d) : "l"(a), "l"(b)); return d;
}
__device__ __forceinline__ ull rcp2(ull a){
    float lo, hi;
    asm("mov.b64 {%0, %1}, %2;" : "=f"(lo), "=f"(hi) : "l"(a));
    lo = rcp_fast(lo); hi = rcp_fast(hi);
    ull d; asm("mov.b64 %0, {%1, %2};" : "=l"(d) : "f"(lo), "f"(hi)); return d;
}
__device__ __forceinline__ ull pk2(float f){
    unsigned u = __float_as_uint(f);
    return (ull)u | ((ull)u << 32);
}
__device__ __forceinline__ void upk2(ull a, float& lo, float& hi){
    asm("mov.b64 {%0, %1}, %2;" : "=f"(lo), "=f"(hi) : "l"(a));
}
__device__ __forceinline__ ull mkp(float lo, float hi){
    ull d; asm("mov.b64 %0, {%1, %2};" : "=l"(d) : "f"(lo), "f"(hi)); return d;
}
#define ONE2 0x3F8000003F800000ULL
#define LOG2E 1.4426950408889634f
#define TWO_LOG2E 2.8853900817779268f
#define EXP_CAP 3.0e4f

// ---------------------------------------------------------------------------
// Kernel 1: split by m. blk&1==0: A = clamp(e^{2*(x@W1^T)}) -> g_A
//                       blk&1==1: u = clamp(e^{2*(x@W2^T)}) -> g_uT (transposed)
// 16 rows per block, one 16KB weight matrix staged per block; grid 512.
// ---------------------------------------------------------------------------
__global__ __launch_bounds__(256) void proj_kernel(const float* __restrict__ x,
                                                   const float* __restrict__ W1,
                                                   const float* __restrict__ W2){
    __shared__ float Ws[64][65];
    __shared__ float xs[16][64];
    __shared__ float us[16][65];
    int t = threadIdx.x;
    int m = blockIdx.x & 1;
    int row0 = (blockIdx.x >> 1) * 16;

    const float4* wv = (const float4*)(m ? W2 : W1);
    #pragma unroll
    for (int p = 0; p < 4; p++){
        int idx = p*256 + t;
        int d = idx >> 4, c4 = (idx & 15) * 4;
        float4 v = wv[idx];
        Ws[d][c4+0]=v.x; Ws[d][c4+1]=v.y; Ws[d][c4+2]=v.z; Ws[d][c4+3]=v.w;
    }
    {
        int rl = t >> 4, c4 = (t & 15) * 4;
        float4 v = ((const float4*)(x + (size_t)(row0+rl)*CC))[t & 15];
        xs[rl][c4+0]=v.x; xs[rl][c4+1]=v.y; xs[rl][c4+2]=v.z; xs[rl][c4+3]=v.w;
    }
    __syncthreads();

    int rg = t >> 6;          // 0..3
    int d  = t & 63;
    #pragma unroll
    for (int it = 0; it < 4; it++){
        int rl = it*4 + rg;
        float acc = 0.f;
        #pragma unroll
        for (int c = 0; c < 64; c++)
            acc = fmaf(xs[rl][c], Ws[d][c], acc);
        float e = fminf(ex2_fast(acc * TWO_LOG2E), EXP_CAP);
        if (m == 0) g_A[(size_t)(row0+rl)*CC + d] = e;
        else        us[rl][d] = e;
    }
    if (m == 1){
        __syncthreads();
        int b = row0 >> 10;
        int row0b = row0 & (NN-1);
        int c = t >> 2, q = t & 3;
        float4 v = make_float4(us[4*q+0][c], us[4*q+1][c], us[4*q+2][c], us[4*q+3][c]);
        *(float4*)(g_uT + (size_t)b*CC*NN + (size_t)c*NN + row0b + 4*q) = v;
    }
}

// ---------------------------------------------------------------------------
// Kernel 2 (FUSED logits + softmax):
//   logit[b,i,j] = S + sum_c w'_c / (1 + A[i,c]*u[j,c]), w' = -2*w3, S = sum w3
//   Block = (b, 8 i-rows); warp per i-row; loops over all 8 j-tiles so each
//   lane ends with its full 32 j-values in registers -> shfl-only softmax,
//   single normalized write (no separate softmax pass, no logit round-trip).
// ---------------------------------------------------------------------------
__global__ __launch_bounds__(256) void logits_kernel(const float* __restrict__ w3f,
                                                     float* __restrict__ out){
    __shared__ float      ut[CC][JC];     // 32KB
    __shared__ ulonglong2 aw[IB][CC];     // (A,A | w',w') 8KB
    __shared__ float      w3lin[CC];

    int t = threadIdx.x;
    int lane = t & 31, il = t >> 5;       // warp = i-row
    int blk = blockIdx.x;                 // 0..511
    int b  = blk >> 7;
    int ih = blk & 127;
    int i0 = ih * IB;

    if (t < 128){
        int ii = t >> 4, c4 = (t & 15) * 4;
        float4 a4 = ((const float4*)(g_A + ((size_t)b*NN + i0 + ii)*CC))[t & 15];
        float4 w4 = ((const float4*)w3f)[t & 15];
        aw[ii][c4+0] = make_ulonglong2(pk2(a4.x), pk2(-2.0f*w4.x));
        aw[ii][c4+1] = make_ulonglong2(pk2(a4.y), pk2(-2.0f*w4.y));
        aw[ii][c4+2] = make_ulonglong2(pk2(a4.z), pk2(-2.0f*w4.z));
        aw[ii][c4+3] = make_ulonglong2(pk2(a4.w), pk2(-2.0f*w4.w));
    } else if (t < 192){
        w3lin[t-128] = w3f[t-128];
    }

    float S = 0.f;   // computed after first sync (w3lin ready then)
    int jb = 4*lane;
    ull acc[16];

    const float* uTb = g_uT + (size_t)b*CC*NN;

    #pragma unroll 1
    for (int jt = 0; jt < 8; jt++){
        __syncthreads();
        // stage u tile [64][128] for j0 = jt*128: coalesced, conflict-free
        {
            const float* uTbase = uTb + jt*JC;
            #pragma unroll
            for (int k = 0; k < 8; k++){
                int idx = k*256 + t;
                int c = idx >> 5, j4 = idx & 31;
                float4 v = *(const float4*)(uTbase + (size_t)c*NN + 4*j4);
                *(float4*)&ut[c][4*j4] = v;
            }
        }
        __syncthreads();
        if (jt == 0){
            #pragma unroll
            for (int c = 0; c < CC; c++) S += w3lin[c];
        }

        ull a0 = pk2(S), a1 = pk2(S);
        #pragma unroll
        for (int g = 0; g < 16; g++){
            int c = g*4;
            ulonglong2 aw0 = aw[il][c+0];
            ulonglong2 aw1 = aw[il][c+1];
            ulonglong2 aw2 = aw[il][c+2];
            ulonglong2 aw3 = aw[il][c+3];
            ulonglong2 U0 = *(const ulonglong2*)&ut[c+0][jb];
            ulonglong2 U1 = *(const ulonglong2*)&ut[c+1][jb];
            ulonglong2 U2 = *(const ulonglong2*)&ut[c+2][jb];
            ulonglong2 U3 = *(const ulonglong2*)&ut[c+3][jb];
            {
                ull D0 = fma2(aw0.x, U0.x, ONE2);
                ull D1 = fma2(aw1.x, U1.x, ONE2);
                ull D2 = fma2(aw2.x, U2.x, ONE2);
                ull D3 = fma2(aw3.x, U3.x, ONE2);
                ull n01 = fma2(aw0.y, D1, mul2(aw1.y, D0));
                ull d01 = mul2(D0, D1);
                ull n23 = fma2(aw2.y, D3, mul2(aw3.y, D2));
                ull d23 = mul2(D2, D3);
                ull nf  = fma2(n01, d23, mul2(n23, d01));
                ull df  = mul2(d01, d23);
                a0 = fma2(nf, rcp2(df), a0);
            }
            {
                ull D0 = fma2(aw0.x, U0.y, ONE2);
                ull D1 = fma2(aw1.x, U1.y, ONE2);
                ull D2 = fma2(aw2.x, U2.y, ONE2);
                ull D3 = fma2(aw3.x, U3.y, ONE2);
                ull n01 = fma2(aw0.y, D1, mul2(aw1.y, D0));
                ull d01 = mul2(D0, D1);
                ull n23 = fma2(aw2.y, D3, mul2(aw3.y, D2));
                ull d23 = mul2(D2, D3);
                ull nf  = fma2(n01, d23, mul2(n23, d01));
                ull df  = mul2(d01, d23);
                a1 = fma2(nf, rcp2(df), a1);
            }
        }
        acc[2*jt]   = a0;
        acc[2*jt+1] = a1;
    }

    // ---- in-register row softmax (warp owns full row of 1024: 32 vals/lane)
    float m = -3.4e38f;
    #pragma unroll
    for (int k = 0; k < 16; k++){
        float lo, hi; upk2(acc[k], lo, hi);
        m = fmaxf(m, fmaxf(lo, hi));
    }
    #pragma unroll
    for (int o = 16; o; o >>= 1) m = fmaxf(m, __shfl_xor_sync(0xffffffffu, m, o));

    float s = 0.f;
    float ex[32];
    #pragma unroll
    for (int k = 0; k < 16; k++){
        float lo, hi; upk2(acc[k], lo, hi);
        lo = ex2_fast((lo - m)*LOG2E);
        hi = ex2_fast((hi - m)*LOG2E);
        ex[2*k] = lo; ex[2*k+1] = hi;
        s += lo + hi;
    }
    #pragma unroll
    for (int o = 16; o; o >>= 1) s += __shfl_xor_sync(0xffffffffu, s, o);
    float inv = 1.0f / s;

    float* orow = out + ((size_t)(b*NN + i0 + il))*NN;
    #pragma unroll
    for (int jt = 0; jt < 8; jt++){
        ull r0 = mkp(ex[4*jt+0]*inv, ex[4*jt+1]*inv);
        ull r1 = mkp(ex[4*jt+2]*inv, ex[4*jt+3]*inv);
        *(ulonglong2*)(orow + jt*JC + jb) = make_ulonglong2(r0, r1);
    }
}

// ---------------------------------------------------------------------------
extern "C" void kernel_launch(void* const* d_in, const int* in_sizes, int n_in,
                              void* d_out, int out_size){
    const float* x  = (const float*)d_in[0];
    const float* W1 = (const float*)d_in[1];
    const float* W2 = (const float*)d_in[2];
    const float* w3 = (const float*)d_in[3];
    float* out = (float*)d_out;

    proj_kernel<<<(ROWS/16)*2, 256>>>(x, W1, W2);
    logits_kernel<<<BN*128, 256>>>(w3, out);
}

// round 12
// speedup vs baseline: 1.1894x; 1.1894x over previous
#include <cuda_runtime.h>
#include <cstddef>

#define BN 4
#define NN 1024
#define CC 64
#define ROWS (BN*NN)   // 4096
#define IB 16          // i-rows per logits block (2 rows per warp)
#define JC 128         // j per tile

typedef unsigned long long ull;

// device scratch (no allocation allowed)
__device__ float g_A [ROWS*CC];          // e^{2*z1}, clamped, [b*N+i][c]
__device__ float g_uT[BN*CC*NN];         // e^{2*z2}, clamped, transposed [b][c][j]

__device__ __forceinline__ float rcp_fast(float x){
    float y; asm("rcp.approx.f32 %0, %1;" : "=f"(y) : "f"(x)); return y;
}
__device__ __forceinline__ float ex2_fast(float x){
    float y; asm("ex2.approx.f32 %0, %1;" : "=f"(y) : "f"(x)); return y;
}
__device__ __forceinline__ ull fma2(ull a, ull b, ull c){
    ull d; asm("fma.rn.f32x2 %0, %1, %2, %3;" : "=l"(d) : "l"(a), "l"(b), "l"(c)); return d;
}
__device__ __forceinline__ ull mul2(ull a, ull b){
    ull d; asm("mul.rn.f32x2 %0, %1, %2;" : "=l"(d) : "l"(a), "l"(b)); return d;
}
__device__ __forceinline__ ull rcp2(ull a){
    float lo, hi;
    asm("mov.b64 {%0, %1}, %2;" : "=f"(lo), "=f"(hi) : "l"(a));
    lo = rcp_fast(lo); hi = rcp_fast(hi);
    ull d; asm("mov.b64 %0, {%1, %2};" : "=l"(d) : "f"(lo), "f"(hi)); return d;
}
__device__ __forceinline__ ull pk2(float f){
    unsigned u = __float_as_uint(f);
    return (ull)u | ((ull)u << 32);
}
#define ONE2 0x3F8000003F800000ULL
#define LOG2E 1.4426950408889634f
#define TWO_LOG2E 2.8853900817779268f
#define EXP_CAP 3.0e4f

// ---------------------------------------------------------------------------
// Kernel 1 (R11 split version, ~5us): blk&1 selects W1->g_A or W2->g_uT.
// ---------------------------------------------------------------------------
__global__ __launch_bounds__(256) void proj_kernel(const float* __restrict__ x,
                                                   const float* __restrict__ W1,
                                                   const float* __restrict__ W2){
    __shared__ float Ws[64][65];
    __shared__ float xs[16][64];
    __shared__ float us[16][65];
    int t = threadIdx.x;
    int m = blockIdx.x & 1;
    int row0 = (blockIdx.x >> 1) * 16;

    const float4* wv = (const float4*)(m ? W2 : W1);
    #pragma unroll
    for (int p = 0; p < 4; p++){
        int idx = p*256 + t;
        int d = idx >> 4, c4 = (idx & 15) * 4;
        float4 v = wv[idx];
        Ws[d][c4+0]=v.x; Ws[d][c4+1]=v.y; Ws[d][c4+2]=v.z; Ws[d][c4+3]=v.w;
    }
    {
        int rl = t >> 4, c4 = (t & 15) * 4;
        float4 v = ((const float4*)(x + (size_t)(row0+rl)*CC))[t & 15];
        xs[rl][c4+0]=v.x; xs[rl][c4+1]=v.y; xs[rl][c4+2]=v.z; xs[rl][c4+3]=v.w;
    }
    __syncthreads();

    int rg = t >> 6;          // 0..3
    int d  = t & 63;
    #pragma unroll
    for (int it = 0; it < 4; it++){
        int rl = it*4 + rg;
        float acc = 0.f;
        #pragma unroll
        for (int c = 0; c < 64; c++)
            acc = fmaf(xs[rl][c], Ws[d][c], acc);
        float e = fminf(ex2_fast(acc * TWO_LOG2E), EXP_CAP);
        if (m == 0) g_A[(size_t)(row0+rl)*CC + d] = e;
        else        us[rl][d] = e;
    }
    if (m == 1){
        __syncthreads();
        int b = row0 >> 10;
        int row0b = row0 & (NN-1);
        int c = t >> 2, q = t & 3;
        float4 v = make_float4(us[4*q+0][c], us[4*q+1][c], us[4*q+2][c], us[4*q+3][c]);
        *(float4*)(g_uT + (size_t)b*CC*NN + (size_t)c*NN + row0b + 4*q) = v;
    }
}

// ---------------------------------------------------------------------------
// Kernel 2: logits[b,i,j] = S + sum_c w'_c / (1 + A[i,c]*u[j,c])
// TWO i-rows per warp: each U LDS.128 feeds 16 terms (2i x 8j) -> LDS data
// traffic halved vs 1 row/warp. grid = 4b x 64ih x 8jt = 2048 blocks.
// ---------------------------------------------------------------------------
__global__ __launch_bounds__(256) void logits_kernel(const float* __restrict__ w3f,
                                                     float* __restrict__ out){
    __shared__ float      ut[CC][JC];     // 32KB
    __shared__ ulonglong2 aw[IB][CC];     // (A,A | w',w') 16KB
    __shared__ float      w3lin[CC];

    int t = threadIdx.x;
    int lane = t & 31, w = t >> 5;        // warp handles rows 2w, 2w+1
    int blk = blockIdx.x;
    int b  = blk >> 9;
    int ih = (blk >> 3) & 63;
    int jt = blk & 7;
    int i0 = ih * IB;
    int j0 = jt * JC;

    // stage u tile [64][128]: coalesced, conflict-free
    const float* uTbase = g_uT + (size_t)b*CC*NN + j0;
    #pragma unroll
    for (int k = 0; k < 8; k++){
        int idx = k*256 + t;
        int c = idx >> 5, j4 = idx & 31;
        float4 v = *(const float4*)(uTbase + (size_t)c*NN + 4*j4);
        *(float4*)&ut[c][4*j4] = v;
    }
    // stage (A, w') for 16 rows: 256 threads x 4 channels
    {
        int ii = t >> 4, c4 = (t & 15) * 4;
        float4 a4 = ((const float4*)(g_A + ((size_t)b*NN + i0 + ii)*CC))[t & 15];
        float4 w4 = ((const float4*)w3f)[t & 15];
        aw[ii][c4+0] = make_ulonglong2(pk2(a4.x), pk2(-2.0f*w4.x));
        aw[ii][c4+1] = make_ulonglong2(pk2(a4.y), pk2(-2.0f*w4.y));
        aw[ii][c4+2] = make_ulonglong2(pk2(a4.z), pk2(-2.0f*w4.z));
        aw[ii][c4+3] = make_ulonglong2(pk2(a4.w), pk2(-2.0f*w4.w));
    }
    if (t < CC) w3lin[t] = w3f[t];
    __syncthreads();

    float S = 0.f;
    #pragma unroll
    for (int c = 0; c < CC; c++) S += w3lin[c];

    int jb = 4*lane;
    int r0 = 2*w, r1 = 2*w + 1;
    ull accA0 = pk2(S), accA1 = pk2(S);   // row r0: j(jb,jb+1), (jb+2,jb+3)
    ull accB0 = pk2(S), accB1 = pk2(S);   // row r1

    #pragma unroll
    for (int g = 0; g < 16; g++){
        int c = g*4;
        ulonglong2 U0 = *(const ulonglong2*)&ut[c+0][jb];
        ulonglong2 U1 = *(const ulonglong2*)&ut[c+1][jb];
        ulonglong2 U2 = *(const ulonglong2*)&ut[c+2][jb];
        ulonglong2 U3 = *(const ulonglong2*)&ut[c+3][jb];
        // ---- row r0
        {
            ulonglong2 aw0 = aw[r0][c+0];
            ulonglong2 aw1 = aw[r0][c+1];
            ulonglong2 aw2 = aw[r0][c+2];
            ulonglong2 aw3 = aw[r0][c+3];
            {
                ull D0 = fma2(aw0.x, U0.x, ONE2);
                ull D1 = fma2(aw1.x, U1.x, ONE2);
                ull D2 = fma2(aw2.x, U2.x, ONE2);
                ull D3 = fma2(aw3.x, U3.x, ONE2);
                ull n01 = fma2(aw0.y, D1, mul2(aw1.y, D0));
                ull d01 = mul2(D0, D1);
                ull n23 = fma2(aw2.y, D3, mul2(aw3.y, D2));
                ull d23 = mul2(D2, D3);
                ull nf  = fma2(n01, d23, mul2(n23, d01));
                accA0 = fma2(nf, rcp2(mul2(d01, d23)), accA0);
            }
            {
                ull D0 = fma2(aw0.x, U0.y, ONE2);
                ull D1 = fma2(aw1.x, U1.y, ONE2);
                ull D2 = fma2(aw2.x, U2.y, ONE2);
                ull D3 = fma2(aw3.x, U3.y, ONE2);
                ull n01 = fma2(aw0.y, D1, mul2(aw1.y, D0));
                ull d01 = mul2(D0, D1);
                ull n23 = fma2(aw2.y, D3, mul2(aw3.y, D2));
                ull d23 = mul2(D2, D3);
                ull nf  = fma2(n01, d23, mul2(n23, d01));
                accA1 = fma2(nf, rcp2(mul2(d01, d23)), accA1);
            }
        }
        // ---- row r1 (reuses U0..U3)
        {
            ulonglong2 aw0 = aw[r1][c+0];
            ulonglong2 aw1 = aw[r1][c+1];
            ulonglong2 aw2 = aw[r1][c+2];
            ulonglong2 aw3 = aw[r1][c+3];
            {
                ull D0 = fma2(aw0.x, U0.x, ONE2);
                ull D1 = fma2(aw1.x, U1.x, ONE2);
                ull D2 = fma2(aw2.x, U2.x, ONE2);
                ull D3 = fma2(aw3.x, U3.x, ONE2);
                ull n01 = fma2(aw0.y, D1, mul2(aw1.y, D0));
                ull d01 = mul2(D0, D1);
                ull n23 = fma2(aw2.y, D3, mul2(aw3.y, D2));
                ull d23 = mul2(D2, D3);
                ull nf  = fma2(n01, d23, mul2(n23, d01));
                accB0 = fma2(nf, rcp2(mul2(d01, d23)), accB0);
            }
            {
                ull D0 = fma2(aw0.x, U0.y, ONE2);
                ull D1 = fma2(aw1.x, U1.y, ONE2);
                ull D2 = fma2(aw2.x, U2.y, ONE2);
                ull D3 = fma2(aw3.x, U3.y, ONE2);
                ull n01 = fma2(aw0.y, D1, mul2(aw1.y, D0));
                ull d01 = mul2(D0, D1);
                ull n23 = fma2(aw2.y, D3, mul2(aw3.y, D2));
                ull d23 = mul2(D2, D3);
                ull nf  = fma2(n01, d23, mul2(n23, d01));
                accB1 = fma2(nf, rcp2(mul2(d01, d23)), accB1);
            }
        }
    }
    float* orow0 = out + ((size_t)(b*NN + i0 + r0))*NN + j0;
    float* orow1 = out + ((size_t)(b*NN + i0 + r1))*NN + j0;
    *(ulonglong2*)(orow0 + jb) = make_ulonglong2(accA0, accA1);
    *(ulonglong2*)(orow1 + jb) = make_ulonglong2(accB0, accB1);
}

// ---------------------------------------------------------------------------
// Kernel 3: in-place row softmax, WARP per row (R10 version, ~5.5us).
// ---------------------------------------------------------------------------
__global__ __launch_bounds__(256) void softmax_kernel(float* __restrict__ out){
    int t = threadIdx.x, lane = t & 31, w = t >> 5;
    size_t row = (size_t)blockIdx.x * 8 + w;
    float4* p = (float4*)out + row*(NN/4);

    float4 v[8];
    #pragma unroll
    for (int k = 0; k < 8; k++) v[k] = p[k*32 + lane];

    float m = -3.4e38f;
    #pragma unroll
    for (int k = 0; k < 8; k++)
        m = fmaxf(m, fmaxf(fmaxf(v[k].x, v[k].y), fmaxf(v[k].z, v[k].w)));
    #pragma unroll
    for (int o = 16; o; o >>= 1) m = fmaxf(m, __shfl_xor_sync(0xffffffffu, m, o));

    float s = 0.f;
    #pragma unroll
    for (int k = 0; k < 8; k++){
        v[k].x = ex2_fast((v[k].x - m)*LOG2E);
        v[k].y = ex2_fast((v[k].y - m)*LOG2E);
        v[k].z = ex2_fast((v[k].z - m)*LOG2E);
        v[k].w = ex2_fast((v[k].w - m)*LOG2E);
        s += (v[k].x + v[k].y) + (v[k].z + v[k].w);
    }
    #pragma unroll
    for (int o = 16; o; o >>= 1) s += __shfl_xor_sync(0xffffffffu, s, o);

    float inv = 1.0f / s;
    #pragma unroll
    for (int k = 0; k < 8; k++){
        v[k].x *= inv; v[k].y *= inv; v[k].z *= inv; v[k].w *= inv;
        p[k*32 + lane] = v[k];
    }
}

// ---------------------------------------------------------------------------
extern "C" void kernel_launch(void* const* d_in, const int* in_sizes, int n_in,
                              void* d_out, int out_size){
    const float* x  = (const float*)d_in[0];
    const float* W1 = (const float*)d_in[1];
    const float* W2 = (const float*)d_in[2];
    const float* w3 = (const float*)d_in[3];
    float* out = (float*)d_out;

    proj_kernel<<<(ROWS/16)*2, 256>>>(x, W1, W2);
    logits_kernel<<<BN*64*8, 256>>>(w3, out);
    softmax_kernel<<<ROWS/8, 256>>>(out);
}

// round 13
// speedup vs baseline: 1.2178x; 1.0238x over previous
#include <cuda_runtime.h>
#include <cstddef>

#define BN 4
#define NN 1024
#define CC 64
#define ROWS (BN*NN)   // 4096
#define IB 16          // i-rows per logits block (2 rows per warp)
#define JC 128         // j per tile
#define PR 64          // proj rows per block

typedef unsigned long long ull;

// device scratch (no allocation allowed)
__device__ float g_A [ROWS*CC];          // e^{2*z1}, clamped, [b*N+i][c]
__device__ float g_uT[BN*CC*NN];         // e^{2*z2}, clamped, transposed [b][c][j]

__device__ __forceinline__ float rcp_fast(float x){
    float y; asm("rcp.approx.f32 %0, %1;" : "=f"(y) : "f"(x)); return y;
}
__device__ __forceinline__ float ex2_fast(float x){
    float y; asm("ex2.approx.f32 %0, %1;" : "=f"(y) : "f"(x)); return y;
}
__device__ __forceinline__ ull fma2(ull a, ull b, ull c){
    ull d; asm("fma.rn.f32x2 %0, %1, %2, %3;" : "=l"(d) : "l"(a), "l"(b), "l"(c)); return d;
}
__device__ __forceinline__ ull mul2(ull a, ull b){
    ull d; asm("mul.rn.f32x2 %0, %1, %2;" : "=l"(d) : "l"(a), "l"(b)); return d;
}
__device__ __forceinline__ ull rcp2(ull a){
    float lo, hi;
    asm("mov.b64 {%0, %1}, %2;" : "=f"(lo), "=f"(hi) : "l"(a));
    lo = rcp_fast(lo); hi = rcp_fast(hi);
    ull d; asm("mov.b64 %0, {%1, %2};" : "=l"(d) : "f"(lo), "f"(hi)); return d;
}
__device__ __forceinline__ ull pk2(float f){
    unsigned u = __float_as_uint(f);
    return (ull)u | ((ull)u << 32);
}
#define ONE2 0x3F8000003F800000ULL
#define LOG2E 1.4426950408889634f
#define TWO_LOG2E 2.8853900817779268f
#define EXP_CAP 3.0e4f

// ---------------------------------------------------------------------------
// Kernel 1: 64 rows per block, grid 128 (~1 wave). blk&1 selects
// W1 -> g_A  or  W2 -> g_uT (fused transpose). Weights staged ONCE per block.
// ---------------------------------------------------------------------------
__global__ __launch_bounds__(256) void proj_kernel(const float* __restrict__ x,
                                                   const float* __restrict__ W1,
                                                   const float* __restrict__ W2){
    __shared__ float Ws[64][65];
    __shared__ float xs[PR][64];
    __shared__ float us[PR][65];
    int t = threadIdx.x;
    int m = blockIdx.x & 1;
    int row0 = (blockIdx.x >> 1) * PR;

    const float4* wv = (const float4*)(m ? W2 : W1);
    #pragma unroll
    for (int p = 0; p < 4; p++){
        int idx = p*256 + t;
        int d = idx >> 4, c4 = (idx & 15) * 4;
        float4 v = wv[idx];
        Ws[d][c4+0]=v.x; Ws[d][c4+1]=v.y; Ws[d][c4+2]=v.z; Ws[d][c4+3]=v.w;
    }
    #pragma unroll
    for (int p = 0; p < 4; p++){        // 1024 float4 = 64 rows x 16
        int idx = p*256 + t;
        int rl = idx >> 4, c4 = (idx & 15) * 4;
        float4 v = ((const float4*)(x + (size_t)(row0+rl)*CC))[idx & 15];
        xs[rl][c4+0]=v.x; xs[rl][c4+1]=v.y; xs[rl][c4+2]=v.z; xs[rl][c4+3]=v.w;
    }
    __syncthreads();

    int rg = t >> 6;          // 0..3
    int d  = t & 63;
    #pragma unroll 4
    for (int it = 0; it < 16; it++){
        int rl = it*4 + rg;
        float acc = 0.f;
        #pragma unroll
        for (int c = 0; c < 64; c++)
            acc = fmaf(xs[rl][c], Ws[d][c], acc);
        float e = fminf(ex2_fast(acc * TWO_LOG2E), EXP_CAP);
        if (m == 0) g_A[(size_t)(row0+rl)*CC + d] = e;
        else        us[rl][d] = e;
    }
    if (m == 1){
        __syncthreads();
        int b = row0 >> 10;
        int row0b = row0 & (NN-1);
        int c = t >> 2, q = t & 3;       // c in [0,64), q selects 16 j's
        float* dst = g_uT + (size_t)b*CC*NN + (size_t)c*NN + row0b + 16*q;
        #pragma unroll
        for (int p = 0; p < 4; p++){
            int j = 16*q + 4*p;
            float4 v = make_float4(us[j+0][c], us[j+1][c], us[j+2][c], us[j+3][c]);
            *(float4*)(dst + 4*p) = v;
        }
    }
}

// ---------------------------------------------------------------------------
// Kernel 2: logits[b,i,j] = S + sum_c w'_c / (1 + A[i,c]*u[j,c])
// 2 i-rows per warp (U reuse). smem diet: per-row A table + SHARED w' table
// (was duplicated per row) -> 41KB total, 4 blocks/SM by regs.
// ---------------------------------------------------------------------------
__global__ __launch_bounds__(256) void logits_kernel(const float* __restrict__ w3f,
                                                     float* __restrict__ out){
    __shared__ float ut[CC][JC];     // 32KB
    __shared__ ull   A2[IB][CC];     // (A,A) per row          8KB
    __shared__ ull   wp[CC];         // (w',w') shared         512B
    __shared__ float w3lin[CC];

    int t = threadIdx.x;
    int lane = t & 31, w = t >> 5;        // warp handles rows 2w, 2w+1
    int blk = blockIdx.x;
    int b  = blk >> 9;
    int ih = (blk >> 3) & 63;
    int jt = blk & 7;
    int i0 = ih * IB;
    int j0 = jt * JC;

    // stage u tile [64][128]: coalesced, conflict-free
    const float* uTbase = g_uT + (size_t)b*CC*NN + j0;
    #pragma unroll
    for (int k = 0; k < 8; k++){
        int idx = k*256 + t;
        int c = idx >> 5, j4 = idx & 31;
        float4 v = *(const float4*)(uTbase + (size_t)c*NN + 4*j4);
        *(float4*)&ut[c][4*j4] = v;
    }
    // stage A (16 rows x 64 c) + w' tables
    {
        int ii = t >> 4, c4 = (t & 15) * 4;
        float4 a4 = ((const float4*)(g_A + ((size_t)b*NN + i0 + ii)*CC))[t & 15];
        A2[ii][c4+0] = pk2(a4.x);
        A2[ii][c4+1] = pk2(a4.y);
        A2[ii][c4+2] = pk2(a4.z);
        A2[ii][c4+3] = pk2(a4.w);
    }
    if (t < CC){
        float wc = w3f[t];
        wp[t] = pk2(-2.0f*wc);
        w3lin[t] = wc;
    }
    __syncthreads();

    float S = 0.f;
    #pragma unroll
    for (int c = 0; c < CC; c++) S += w3lin[c];

    int jb = 4*lane;
    int r0 = 2*w, r1 = 2*w + 1;
    ull accA0 = pk2(S), accA1 = pk2(S);   // row r0
    ull accB0 = pk2(S), accB1 = pk2(S);   // row r1

    #pragma unroll
    for (int g = 0; g < 16; g++){
        int c = g*4;
        ulonglong2 U0 = *(const ulonglong2*)&ut[c+0][jb];
        ulonglong2 U1 = *(const ulonglong2*)&ut[c+1][jb];
        ulonglong2 U2 = *(const ulonglong2*)&ut[c+2][jb];
        ulonglong2 U3 = *(const ulonglong2*)&ut[c+3][jb];
        ull w0 = wp[c+0], w1 = wp[c+1], w2 = wp[c+2], w3v = wp[c+3];
        // ---- row r0
        {
            ull A0 = A2[r0][c+0], A1 = A2[r0][c+1], A2v = A2[r0][c+2], A3 = A2[r0][c+3];
            {
                ull D0 = fma2(A0, U0.x, ONE2);
                ull D1 = fma2(A1, U1.x, ONE2);
                ull D2 = fma2(A2v, U2.x, ONE2);
                ull D3 = fma2(A3, U3.x, ONE2);
                ull n01 = fma2(w0, D1, mul2(w1, D0));
                ull d01 = mul2(D0, D1);
                ull n23 = fma2(w2, D3, mul2(w3v, D2));
                ull d23 = mul2(D2, D3);
                ull nf  = fma2(n01, d23, mul2(n23, d01));
                accA0 = fma2(nf, rcp2(mul2(d01, d23)), accA0);
            }
            {
                ull D0 = fma2(A0, U0.y, ONE2);
                ull D1 = fma2(A1, U1.y, ONE2);
                ull D2 = fma2(A2v, U2.y, ONE2);
                ull D3 = fma2(A3, U3.y, ONE2);
                ull n01 = fma2(w0, D1, mul2(w1, D0));
                ull d01 = mul2(D0, D1);
                ull n23 = fma2(w2, D3, mul2(w3v, D2));
                ull d23 = mul2(D2, D3);
                ull nf  = fma2(n01, d23, mul2(n23, d01));
                accA1 = fma2(nf, rcp2(mul2(d01, d23)), accA1);
            }
        }
        // ---- row r1 (reuses U0..U3, w0..w3)
        {
            ull A0 = A2[r1][c+0], A1 = A2[r1][c+1], A2v = A2[r1][c+2], A3 = A2[r1][c+3];
            {
                ull D0 = fma2(A0, U0.x, ONE2);
                ull D1 = fma2(A1, U1.x, ONE2);
                ull D2 = fma2(A2v, U2.x, ONE2);
                ull D3 = fma2(A3, U3.x, ONE2);
                ull n01 = fma2(w0, D1, mul2(w1, D0));
                ull d01 = mul2(D0, D1);
                ull n23 = fma2(w2, D3, mul2(w3v, D2));
                ull d23 = mul2(D2, D3);
                ull nf  = fma2(n01, d23, mul2(n23, d01));
                accB0 = fma2(nf, rcp2(mul2(d01, d23)), accB0);
            }
            {
                ull D0 = fma2(A0, U0.y, ONE2);
                ull D1 = fma2(A1, U1.y, ONE2);
                ull D2 = fma2(A2v, U2.y, ONE2);
                ull D3 = fma2(A3, U3.y, ONE2);
                ull n01 = fma2(w0, D1, mul2(w1, D0));
                ull d01 = mul2(D0, D1);
                ull n23 = fma2(w2, D3, mul2(w3v, D2));
                ull d23 = mul2(D2, D3);
                ull nf  = fma2(n01, d23, mul2(n23, d01));
                accB1 = fma2(nf, rcp2(mul2(d01, d23)), accB1);
            }
        }
    }
    float* orow0 = out + ((size_t)(b*NN + i0 + r0))*NN + j0;
    float* orow1 = out + ((size_t)(b*NN + i0 + r1))*NN + j0;
    *(ulonglong2*)(orow0 + jb) = make_ulonglong2(accA0, accA1);
    *(ulonglong2*)(orow1 + jb) = make_ulonglong2(accB0, accB1);
}

// ---------------------------------------------------------------------------
// Kernel 3: in-place row softmax, WARP per row.
// ---------------------------------------------------------------------------
__global__ __launch_bounds__(256) void softmax_kernel(float* __restrict__ out){
    int t = threadIdx.x, lane = t & 31, w = t >> 5;
    size_t row = (size_t)blockIdx.x * 8 + w;
    float4* p = (float4*)out + row*(NN/4);

    float4 v[8];
    #pragma unroll
    for (int k = 0; k < 8; k++) v[k] = p[k*32 + lane];

    float m = -3.4e38f;
    #pragma unroll
    for (int k = 0; k < 8; k++)
        m = fmaxf(m, fmaxf(fmaxf(v[k].x, v[k].y), fmaxf(v[k].z, v[k].w)));
    #pragma unroll
    for (int o = 16; o; o >>= 1) m = fmaxf(m, __shfl_xor_sync(0xffffffffu, m, o));

    float s = 0.f;
    #pragma unroll
    for (int k = 0; k < 8; k++){
        v[k].x = ex2_fast((v[k].x - m)*LOG2E);
        v[k].y = ex2_fast((v[k].y - m)*LOG2E);
        v[k].z = ex2_fast((v[k].z - m)*LOG2E);
        v[k].w = ex2_fast((v[k].w - m)*LOG2E);
        s += (v[k].x + v[k].y) + (v[k].z + v[k].w);
    }
    #pragma unroll
    for (int o = 16; o; o >>= 1) s += __shfl_xor_sync(0xffffffffu, s, o);

    float inv = 1.0f / s;
    #pragma unroll
    for (int k = 0; k < 8; k++){
        v[k].x *= inv; v[k].y *= inv; v[k].z *= inv; v[k].w *= inv;
        p[k*32 + lane] = v[k];
    }
}

// ---------------------------------------------------------------------------
extern "C" void kernel_launch(void* const* d_in, const int* in_sizes, int n_in,
                              void* d_out, int out_size){
    const float* x  = (const float*)d_in[0];
    const float* W1 = (const float*)d_in[1];
    const float* W2 = (const float*)d_in[2];
    const float* w3 = (const float*)d_in[3];
    float* out = (float*)d_out;

    proj_kernel<<<(ROWS/PR)*2, 256>>>(x, W1, W2);
    logits_kernel<<<BN*64*8, 256>>>(w3, out);
    softmax_kernel<<<ROWS/8, 256>>>(out);
}

// round 15
// speedup vs baseline: 1.3213x; 1.0850x over previous
#include <cuda_runtime.h>
#include <cstddef>

#define BN 4
#define NN 1024
#define CC 64
#define ROWS (BN*NN)   // 4096
#define IB 16          // i-rows per logits block (2 rows per warp)
#define JC 128         // j per tile
#define PR 16          // proj rows per block

typedef unsigned long long ull;

__device__ float g_A [ROWS*CC];          // e^{2*z1}, clamped, [b*N+i][c]
__device__ float g_uT[BN*CC*NN];         // e^{2*z2}, clamped, transposed [b][c][j]

__device__ __forceinline__ float rcp_fast(float x){
    float y; asm("rcp.approx.f32 %0, %1;" : "=f"(y) : "f"(x)); return y;
}
__device__ __forceinline__ float ex2_fast(float x){
    float y; asm("ex2.approx.f32 %0, %1;" : "=f"(y) : "f"(x)); return y;
}
__device__ __forceinline__ ull fma2(ull a, ull b, ull c){
    ull d; asm("fma.rn.f32x2 %0, %1, %2, %3;" : "=l"(d) : "l"(a), "l"(b), "l"(c)); return d;
}
__device__ __forceinline__ ull mul2(ull a, ull b){
    ull d; asm("mul.rn.f32x2 %0, %1, %2;" : "=l"(d) : "l"(a), "l"(b)); return d;
}
__device__ __forceinline__ ull rcp2(ull a){
    float lo, hi;
    asm("mov.b64 {%0, %1}, %2;" : "=f"(lo), "=f"(hi) : "l"(a));
    lo = rcp_fast(lo); hi = rcp_fast(hi);
    ull d; asm("mov.b64 %0, {%1, %2};" : "=l"(d) : "f"(lo), "f"(hi)); return d;
}
__device__ __forceinline__ ull pk2(float f){
    unsigned u = __float_as_uint(f);
    return (ull)u | ((ull)u << 32);
}
#define ONE2 0x3F8000003F800000ULL
#define LOG2E 1.4426950408889634f
#define TWO_LOG2E 2.8853900817779268f
#define EXP_CAP 3.0e4f
#define SSC 2.44140625e-4f    // 2^-12

// ---------------------------------------------------------------------------
// Kernel 1: BOTH matrices per block, 16 rows, 4-row register blocking.
// thread = (rg, d): 4 rows x 2 matrices = 8 outputs; per c: 2 lane-LDS + 4
// bcast-LDS feed 8 FMAs. grid 256.
// ---------------------------------------------------------------------------
__global__ __launch_bounds__(256) void proj_kernel(const float* __restrict__ x,
                                                   const float* __restrict__ W1,
                                                   const float* __restrict__ W2){
    __shared__ float Ws[2][64][65];
    __shared__ float xs[PR][64];
    __shared__ float us[PR][65];
    int t = threadIdx.x;
    int row0 = blockIdx.x * PR;

    const float4* w1v = (const float4*)W1;
    const float4* w2v = (const float4*)W2;
    #pragma unroll
    for (int p = 0; p < 4; p++){
        int idx = p*256 + t;
        int d = idx >> 4, c4 = (idx & 15) * 4;
        float4 v = w1v[idx];
        Ws[0][d][c4+0]=v.x; Ws[0][d][c4+1]=v.y; Ws[0][d][c4+2]=v.z; Ws[0][d][c4+3]=v.w;
        v = w2v[idx];
        Ws[1][d][c4+0]=v.x; Ws[1][d][c4+1]=v.y; Ws[1][d][c4+2]=v.z; Ws[1][d][c4+3]=v.w;
    }
    {
        int rl = t >> 4, c4 = (t & 15) * 4;
        float4 v = ((const float4*)(x + (size_t)(row0+rl)*CC))[t & 15];
        xs[rl][c4+0]=v.x; xs[rl][c4+1]=v.y; xs[rl][c4+2]=v.z; xs[rl][c4+3]=v.w;
    }
    __syncthreads();

    int rg = t >> 6;          // 0..3 -> rows 4rg..4rg+3
    int d  = t & 63;
    float a10=0.f,a11=0.f,a12=0.f,a13=0.f;   // m=0 accs
    float a20=0.f,a21=0.f,a22=0.f,a23=0.f;   // m=1 accs
    #pragma unroll
    for (int c = 0; c < 64; c++){
        float wa = Ws[0][d][c];
        float wb = Ws[1][d][c];
        float x0 = xs[4*rg+0][c];
        float x1 = xs[4*rg+1][c];
        float x2 = xs[4*rg+2][c];
        float x3 = xs[4*rg+3][c];
        a10 = fmaf(x0, wa, a10); a20 = fmaf(x0, wb, a20);
        a11 = fmaf(x1, wa, a11); a21 = fmaf(x1, wb, a21);
        a12 = fmaf(x2, wa, a12); a22 = fmaf(x2, wb, a22);
        a13 = fmaf(x3, wa, a13); a23 = fmaf(x3, wb, a23);
    }
    {
        float* dA = g_A + (size_t)(row0 + 4*rg)*CC + d;
        dA[0*CC] = fminf(ex2_fast(a10 * TWO_LOG2E), EXP_CAP);
        dA[1*CC] = fminf(ex2_fast(a11 * TWO_LOG2E), EXP_CAP);
        dA[2*CC] = fminf(ex2_fast(a12 * TWO_LOG2E), EXP_CAP);
        dA[3*CC] = fminf(ex2_fast(a13 * TWO_LOG2E), EXP_CAP);
        us[4*rg+0][d] = fminf(ex2_fast(a20 * TWO_LOG2E), EXP_CAP);
        us[4*rg+1][d] = fminf(ex2_fast(a21 * TWO_LOG2E), EXP_CAP);
        us[4*rg+2][d] = fminf(ex2_fast(a22 * TWO_LOG2E), EXP_CAP);
        us[4*rg+3][d] = fminf(ex2_fast(a23 * TWO_LOG2E), EXP_CAP);
    }
    __syncthreads();
    {   // write u transposed: g_uT[b][c][row0b + 0..15]
        int b = row0 >> 10;
        int row0b = row0 & (NN-1);
        int c = t >> 2, q = t & 3;
        float4 v = make_float4(us[4*q+0][c], us[4*q+1][c], us[4*q+2][c], us[4*q+3][c]);
        *(float4*)(g_uT + (size_t)b*CC*NN + (size_t)c*NN + row0b + 4*q) = v;
    }
}

// ---------------------------------------------------------------------------
// Kernel 2: logits[b,i,j] = S + sum_c w'_c / (1 + A[i,c]*u[j,c])
// 8-channel scaled common-denominator tree: Ds_c = s + (s*A_c)*u_c, s=2^-12.
// n8/d8 = s^-1 * true partial sum -> acc init S/s, final *s. 1 rcp2 / 8ch.
// 2 i-rows per warp (U reuse). grid = 4b x 64ih x 8jt = 2048.
// ---------------------------------------------------------------------------
__global__ __launch_bounds__(256) void logits_kernel(const float* __restrict__ w3f,
                                                     float* __restrict__ out){
    __shared__ float ut[CC][JC];     // 32KB
    __shared__ ull   A2[IB][CC];     // (sA, sA) per row   8KB
    __shared__ ull   wp[CC];         // (w',w')            512B
    __shared__ float w3lin[CC];

    int t = threadIdx.x;
    int lane = t & 31, w = t >> 5;
    int blk = blockIdx.x;
    int b  = blk >> 9;
    int ih = (blk >> 3) & 63;
    int jt = blk & 7;
    int i0 = ih * IB;
    int j0 = jt * JC;

    const float* uTbase = g_uT + (size_t)b*CC*NN + j0;
    #pragma unroll
    for (int k = 0; k < 8; k++){
        int idx = k*256 + t;
        int c = idx >> 5, j4 = idx & 31;
        float4 v = *(const float4*)(uTbase + (size_t)c*NN + 4*j4);
        *(float4*)&ut[c][4*j4] = v;
    }
    {
        int ii = t >> 4, c4 = (t & 15) * 4;
        float4 a4 = ((const float4*)(g_A + ((size_t)b*NN + i0 + ii)*CC))[t & 15];
        A2[ii][c4+0] = pk2(SSC*a4.x);
        A2[ii][c4+1] = pk2(SSC*a4.y);
        A2[ii][c4+2] = pk2(SSC*a4.z);
        A2[ii][c4+3] = pk2(SSC*a4.w);
    }
    if (t < CC){
        float wc = w3f[t];
        wp[t] = pk2(-2.0f*wc);
        w3lin[t] = wc;
    }
    __syncthreads();

    float S = 0.f;
    #pragma unroll
    for (int c = 0; c < CC; c++) S += w3lin[c];
    const ull S2 = pk2(SSC);             // packed s

    int jb = 4*lane;
    int r0 = 2*w, r1 = 2*w + 1;
    ull accA0 = pk2(S*4096.0f), accA1 = accA0;   // S/s
    ull accB0 = accA0, accB1 = accA0;

    #pragma unroll
    for (int g = 0; g < 8; g++){
        int c = g*8;
        ulonglong2 U0 = *(const ulonglong2*)&ut[c+0][jb];
        ulonglong2 U1 = *(const ulonglong2*)&ut[c+1][jb];
        ulonglong2 U2 = *(const ulonglong2*)&ut[c+2][jb];
        ulonglong2 U3 = *(const ulonglong2*)&ut[c+3][jb];
        ulonglong2 U4 = *(const ulonglong2*)&ut[c+4][jb];
        ulonglong2 U5 = *(const ulonglong2*)&ut[c+5][jb];
        ulonglong2 U6 = *(const ulonglong2*)&ut[c+6][jb];
        ulonglong2 U7 = *(const ulonglong2*)&ut[c+7][jb];
        ull w0 = wp[c+0], w1 = wp[c+1], w2 = wp[c+2], w3v = wp[c+3];
        ull w4 = wp[c+4], w5 = wp[c+5], w6 = wp[c+6], w7 = wp[c+7];

        #pragma unroll
        for (int r = 0; r < 2; r++){
            int row = r ? r1 : r0;
            ull sA0 = A2[row][c+0], sA1 = A2[row][c+1], sA2 = A2[row][c+2], sA3 = A2[row][c+3];
            ull sA4 = A2[row][c+4], sA5 = A2[row][c+5], sA6 = A2[row][c+6], sA7 = A2[row][c+7];
            #pragma unroll
            for (int p = 0; p < 2; p++){
                ull u0 = p ? U0.y : U0.x;
                ull u1 = p ? U1.y : U1.x;
                ull u2 = p ? U2.y : U2.x;
                ull u3 = p ? U3.y : U3.x;
                ull u4 = p ? U4.y : U4.x;
                ull u5 = p ? U5.y : U5.x;
                ull u6 = p ? U6.y : U6.x;
                ull u7 = p ? U7.y : U7.x;
                ull D0 = fma2(sA0, u0, S2);
                ull D1 = fma2(sA1, u1, S2);
                ull D2 = fma2(sA2, u2, S2);
                ull D3 = fma2(sA3, u3, S2);
                ull D4 = fma2(sA4, u4, S2);
                ull D5 = fma2(sA5, u5, S2);
                ull D6 = fma2(sA6, u6, S2);
                ull D7 = fma2(sA7, u7, S2);
                ull n01 = fma2(w0, D1, mul2(w1, D0));
                ull d01 = mul2(D0, D1);
                ull n23 = fma2(w2, D3, mul2(w3v, D2));
                ull d23 = mul2(D2, D3);
                ull n45 = fma2(w4, D5, mul2(w5, D4));
                ull d45 = mul2(D4, D5);
                ull n67 = fma2(w6, D7, mul2(w7, D6));
                ull d67 = mul2(D6, D7);
                ull nA = fma2(n01, d23, mul2(n23, d01));
                ull dA = mul2(d01, d23);
                ull nB = fma2(n45, d67, mul2(n67, d45));
                ull dB = mul2(d45, d67);
                ull nf = fma2(nA, dB, mul2(nB, dA));
                ull df = mul2(dA, dB);
                ull contrib = mul2(nf, rcp2(df));
                if (r == 0){
                    if (p == 0) accA0 = fma2(contrib, ONE2, accA0);
                    else        accA1 = fma2(contrib, ONE2, accA1);
                } else {
                    if (p == 0) accB0 = fma2(contrib, ONE2, accB0);
                    else        accB1 = fma2(contrib, ONE2, accB1);
                }
            }
        }
    }
    const ull SP = pk2(SSC);
    float* orow0 = out + ((size_t)(b*NN + i0 + r0))*NN + j0;
    float* orow1 = out + ((size_t)(b*NN + i0 + r1))*NN + j0;
    *(ulonglong2*)(orow0 + jb) = make_ulonglong2(mul2(accA0, SP), mul2(accA1, SP));
    *(ulonglong2*)(orow1 + jb) = make_ulonglong2(mul2(accB0, SP), mul2(accB1, SP));
}

// ---------------------------------------------------------------------------
// Kernel 3: in-place row softmax, WARP per row.
// ---------------------------------------------------------------------------
__global__ __launch_bounds__(256) void softmax_kernel(float* __restrict__ out){
    int t = threadIdx.x, lane = t & 31, w = t >> 5;
    size_t row = (size_t)blockIdx.x * 8 + w;
    float4* p = (float4*)out + row*(NN/4);

    float4 v[8];
    #pragma unroll
    for (int k = 0; k < 8; k++) v[k] = p[k*32 + lane];

    float m = -3.4e38f;
    #pragma unroll
    for (int k = 0; k < 8; k++)
        m = fmaxf(m, fmaxf(fmaxf(v[k].x, v[k].y), fmaxf(v[k].z, v[k].w)));
    #pragma unroll
    for (int o = 16; o; o >>= 1) m = fmaxf(m, __shfl_xor_sync(0xffffffffu, m, o));

    float s = 0.f;
    #pragma unroll
    for (int k = 0; k < 8; k++){
        v[k].x = ex2_fast((v[k].x - m)*LOG2E);
        v[k].y = ex2_fast((v[k].y - m)*LOG2E);
        v[k].z = ex2_fast((v[k].z - m)*LOG2E);
        v[k].w = ex2_fast((v[k].w - m)*LOG2E);
        s += (v[k].x + v[k].y) + (v[k].z + v[k].w);
    }
    #pragma unroll
    for (int o = 16; o; o >>= 1) s += __shfl_xor_sync(0xffffffffu, s, o);

    float inv = 1.0f / s;
    #pragma unroll
    for (int k = 0; k < 8; k++){
        v[k].x *= inv; v[k].y *= inv; v[k].z *= inv; v[k].w *= inv;
        p[k*32 + lane] = v[k];
    }
}

// ---------------------------------------------------------------------------
extern "C" void kernel_launch(void* const* d_in, const int* in_sizes, int n_in,
                              void* d_out, int out_size){
    const float* x  = (const float*)d_in[0];
    const float* W1 = (const float*)d_in[1];
    const float* W2 = (const float*)d_in[2];
    const float* w3 = (const float*)d_in[3];
    float* out = (float*)d_out;

    proj_kernel<<<ROWS/PR, 256>>>(x, W1, W2);
    logits_kernel<<<BN*64*8, 256>>>(w3, out);
    softmax_kernel<<<ROWS/8, 256>>>(out);
}